// round 13
// baseline (speedup 1.0000x reference)
#include <cuda_runtime.h>
#include <cuda_fp16.h>
#include <cstdint>

#define N_NODES 100000
#define N_EDGES 1600000
#define F 128
#define SCAN_B 1024
#define NB 98          // ceil(100000/1024)
#define GB_TILES 782   // ceil(100000/128), full 128-col tile
#define ACT_ROWS (N_NODES + 128)          // pad: OOB tile rows stay in-bounds
#define ACT_STRIDE ((size_t)ACT_ROWS * 128)
#define PREPX_ITEMS (N_NODES * 16)
#define PREPW_ITEMS (7 * 128 * 16)

// ---------------- scratch (static __device__, allocation-free) ----------------
// fp16 activation planes, row = 128 fp16 (256B). ids: 0 = x, 1 = xp, 2 = h1, 3 = h2
__device__ __half d_act[4 * ACT_STRIDE];
// weights: 7 slices x [n=128][k=128] fp16
__device__ __half d_wtp[7 * 128 * 128];
__device__ __half d_g[(size_t)N_NODES * F];   // fp16 messages
__device__ float d_dinv[N_NODES];
__device__ int   d_cnt[N_NODES];
__device__ int   d_rowptr[N_NODES + 1];
__device__ int   d_cursor[N_NODES];
__device__ int   d_ssrc[N_EDGES];
__device__ int   d_partial[NB + 1];

__device__ __forceinline__ uint32_t smem_u32(const void* p) {
    uint32_t a;
    asm("{ .reg .u64 t; cvta.to.shared.u64 t, %1; cvt.u32.u64 %0, t; }" : "=r"(a) : "l"(p));
    return a;
}
__device__ __forceinline__ void ldsm_x4(uint32_t* r, uint32_t addr) {
    asm volatile("ldmatrix.sync.aligned.m8n8.x4.shared.b16 {%0,%1,%2,%3}, [%4];"
        : "=r"(r[0]), "=r"(r[1]), "=r"(r[2]), "=r"(r[3]) : "r"(addr));
}
__device__ __forceinline__ void mma16816(float* d, const uint32_t* a, const uint32_t* b) {
    asm volatile(
        "mma.sync.aligned.m16n8k16.row.col.f32.f16.f16.f32 "
        "{%0,%1,%2,%3}, {%4,%5,%6,%7}, {%8,%9}, {%0,%1,%2,%3};"
        : "+f"(d[0]), "+f"(d[1]), "+f"(d[2]), "+f"(d[3])
        : "r"(a[0]), "r"(a[1]), "r"(a[2]), "r"(a[3]), "r"(b[0]), "r"(b[1]));
}
__device__ __forceinline__ void cpa16(uint32_t dst, const void* src) {
    asm volatile("cp.async.cg.shared.global [%0], [%1], 16;" :: "r"(dst), "l"(src));
}
#define CP_COMMIT() asm volatile("cp.async.commit_group;" ::: "memory")
#define CP_WAIT1()  asm volatile("cp.async.wait_group 1;" ::: "memory")
#define CP_WAIT0()  asm volatile("cp.async.wait_group 0;" ::: "memory")

__device__ __forceinline__ uint32_t pack_h2(float x, float y) {
    __half2 t = __floats2half2_rn(x, y);
    return *(uint32_t*)&t;
}
__device__ __forceinline__ float2 unpack_h2(uint32_t v) {
    return __half22float2(*(__half2*)&v);
}

// ---------------- graph preprocessing ----------------
__global__ void k_hist(const int* __restrict__ dst) {
    int e = blockIdx.x * blockDim.x + threadIdx.x;
    if (e < N_EDGES) {
        int d = dst[e];
        if (d >= 0 && d < N_NODES) atomicAdd(&d_cnt[d], 1);
    }
}
__global__ void k_dinv() {
    int v = blockIdx.x * blockDim.x + threadIdx.x;
    if (v < N_NODES) d_dinv[v] = rsqrtf((float)(d_cnt[v] + 1));
}
__global__ void k_partial() {
    __shared__ int s[SCAN_B];
    int i = blockIdx.x * SCAN_B + threadIdx.x;
    s[threadIdx.x] = (i < N_NODES) ? d_cnt[i] : 0;
    __syncthreads();
    for (int off = SCAN_B / 2; off > 0; off >>= 1) {
        if (threadIdx.x < off) s[threadIdx.x] += s[threadIdx.x + off];
        __syncthreads();
    }
    if (threadIdx.x == 0) d_partial[blockIdx.x] = s[0];
}
// warp-shfl exclusive scan over NB partials (single warp)
__global__ void k_scan_partial() {
    int lane = threadIdx.x;   // 32 threads
    int carry = 0;
    for (int base = 0; base < NB; base += 32) {
        int i = base + lane;
        int orig = (i < NB) ? d_partial[i] : 0;
        int v = orig;
#pragma unroll
        for (int off = 1; off < 32; off <<= 1) {
            int t = __shfl_up_sync(0xFFFFFFFFu, v, off);
            if (lane >= off) v += t;
        }
        if (i < NB) d_partial[i] = carry + v - orig;  // exclusive
        carry += __shfl_sync(0xFFFFFFFFu, v, 31);
    }
    if (lane == 0) d_rowptr[N_NODES] = carry;
}
__global__ void k_scan_final() {
    __shared__ int s[SCAN_B];
    int i = blockIdx.x * SCAN_B + threadIdx.x;
    int v = (i < N_NODES) ? d_cnt[i] : 0;
    s[threadIdx.x] = v;
    __syncthreads();
    for (int off = 1; off < SCAN_B; off <<= 1) {
        int t = (threadIdx.x >= off) ? s[threadIdx.x - off] : 0;
        __syncthreads();
        s[threadIdx.x] += t;
        __syncthreads();
    }
    if (i < N_NODES) {
        int excl = s[threadIdx.x] - v + d_partial[blockIdx.x];
        d_rowptr[i] = excl;
        d_cursor[i] = excl;
    }
}
__global__ void k_scatter(const int* __restrict__ src, const int* __restrict__ dst) {
    int e = blockIdx.x * blockDim.x + threadIdx.x;
    if (e < N_EDGES) {
        int d = dst[e];
        int s = src[e];
        if (d >= 0 && d < N_NODES && s >= 0 && s < N_NODES) {
            int pos = atomicAdd(&d_cursor[d], 1);
            d_ssrc[pos] = s;
        }
    }
}

// ---------------- merged prep: x plane + weight planes + zero cnt ----------------
__global__ void k_prep_all(const float* __restrict__ x,
                           const float* __restrict__ pW, const float* __restrict__ w1,
                           const float* __restrict__ w2, const float* __restrict__ w3) {
    int idx = blockIdx.x * blockDim.x + threadIdx.x;
    if (idx < PREPX_ITEMS) {
        int row = idx >> 4;
        int k0 = (idx & 15) * 8;
        const float* src = x + (size_t)row * F + k0;
        uint32_t h[4];
#pragma unroll
        for (int j = 0; j < 4; j++) h[j] = pack_h2(src[j * 2], src[j * 2 + 1]);
        *(uint4*)(d_act + (size_t)row * 128 + k0) = make_uint4(h[0], h[1], h[2], h[3]);
    } else if (idx < PREPX_ITEMS + N_NODES) {
        d_cnt[idx - PREPX_ITEMS] = 0;
    } else {
        int j = idx - PREPX_ITEMS - N_NODES;
        if (j < PREPW_ITEMS) {
            int slice = j >> 11;
            int rem = j & 2047;
            int n = rem >> 4;
            int k0 = (rem & 15) * 8;
            const float* src; int kg0;
            if (slice == 0)      { src = pW; kg0 = 0; }
            else if (slice == 1) { src = w1; kg0 = 0; }
            else if (slice < 4)  { src = w2; kg0 = (slice - 2) * 128; }
            else                 { src = w3; kg0 = (slice - 4) * 128; }
            uint32_t hi[4];
#pragma unroll
            for (int jj = 0; jj < 4; jj++) {
                float a = src[(size_t)(kg0 + k0 + jj * 2) * 128 + n];
                float b = src[(size_t)(kg0 + k0 + jj * 2 + 1) * 128 + n];
                hi[jj] = pack_h2(a, b);
            }
            *(uint4*)(d_wtp + (size_t)slice * 128 * 128 + (size_t)n * 128 + k0) =
                make_uint4(hi[0], hi[1], hi[2], hi[3]);
        }
    }
}

// ---------------- HMMA GEMM, fp16 single-product, 2-stage cp.async, tile 128x128 ----
// stage s at s*32768: A[128 rows][128B] (16KB), W[128 rows][128B] at +16384 (16KB)
#define STAGE_BYTES 32768
#define SMEM_TOTAL (2 * STAGE_BYTES)

// fused=1: grid 2*GB_TILES; half 0 -> wslice0+0, epi 2 (xp); half 1 -> wslice0+1, epi 1 (g)
// epi: 1 = d_g fp16, scale row by dinv; 2 = xp fp16 plane, bias + relu
__global__ __launch_bounds__(256, 2)
void k_mma(int aid0, int aid1, int aid2, int nslices,
           int wslice0, int epi, int fused, const float* __restrict__ bias)
{
    extern __shared__ char smem[];
    const uint32_t sb = smem_u32(smem);
    const int tid = threadIdx.x;
    const int lane = tid & 31;
    const int warp = tid >> 5;
    const int half_id = fused ? (blockIdx.x >= GB_TILES ? 1 : 0) : 0;
    const int bx = fused ? (blockIdx.x - half_id * GB_TILES) : blockIdx.x;
    const int brow = bx * 128;
    const int wbase = wslice0 + half_id;
    const int epi_eff = fused ? (half_id ? 1 : 2) : epi;
    const int warp_m = (warp >> 1) * 32;
    const int warp_n = (warp & 1) * 64;

    float acc[2][8][4];
#pragma unroll
    for (int mb = 0; mb < 2; mb++)
#pragma unroll
        for (int nb = 0; nb < 8; nb++)
#pragma unroll
            for (int q = 0; q < 4; q++) acc[mb][nb][q] = 0.0f;

    const int aids[3] = {aid0, aid1, aid2};
    const int T = nslices * 2;          // k64 chunks

    // staging thread mapping
    const int st_row = tid >> 3;        // 0..31 (+32 per it)
    const int st_ch  = tid & 7;

    // ldmatrix address components
    const int rowA = warp_m + (lane & 15);
    const int swA = rowA & 7;
    const int chA = lane >> 4;
    const int rowB = warp_n + (lane & 7) + ((lane >> 4) << 3);
    const int swB = lane & 7;
    const int chB = (lane >> 3) & 1;

    // ---- stage chunk t (k64 half c of slice s) into buffer buf ----
    auto stage = [&](int t, int buf) {
        int s = t >> 1, c = t & 1;
        const __half* Ag = d_act + (size_t)aids[s] * ACT_STRIDE;
        const __half* Wg = d_wtp + (size_t)(wbase + s) * 128 * 128;
        uint32_t abuf = sb + buf * STAGE_BYTES;
        uint32_t wbuf = abuf + 16384;
#pragma unroll
        for (int it = 0; it < 4; it++) {
            int row = st_row + it * 32;
            const char* src = (const char*)(Ag + (size_t)(brow + row) * 128 + c * 64) + st_ch * 16;
            cpa16(abuf + row * 128 + ((st_ch ^ (row & 7)) << 4), src);
        }
#pragma unroll
        for (int it = 0; it < 4; it++) {
            int n = st_row + it * 32;   // 0..127
            const __half* wrow = Wg + (size_t)n * 128 + c * 64;
            cpa16(wbuf + n * 128 + ((st_ch ^ (n & 7)) << 4), (const char*)wrow + st_ch * 16);
        }
    };

    stage(0, 0); CP_COMMIT();

    for (int t = 0; t < T; t++) {
        const int buf = t & 1;
        if (t + 1 < T) { stage(t + 1, buf ^ 1); CP_COMMIT(); CP_WAIT1(); }
        else           { CP_WAIT0(); }
        __syncthreads();

        const uint32_t abase = sb + buf * STAGE_BYTES + rowA * 128;
        const uint32_t bbase = sb + buf * STAGE_BYTES + 16384 + rowB * 128;
#pragma unroll
        for (int ks = 0; ks < 4; ks++) {
            uint32_t ah[2][4];
            const int lA = ks * 2 + chA;
#pragma unroll
            for (int mb = 0; mb < 2; mb++)
                ldsm_x4(ah[mb], abase + mb * 2048 + ((lA ^ swA) << 4));
            const int lB = ks * 2 + chB;
            uint32_t bh[4][4];
#pragma unroll
            for (int nq = 0; nq < 4; nq++)
                ldsm_x4(bh[nq], bbase + nq * 2048 + ((lB ^ swB) << 4));
            // 16 MMAs, 16 distinct accumulators
#pragma unroll
            for (int nq = 0; nq < 4; nq++)
#pragma unroll
                for (int mb = 0; mb < 2; mb++) {
                    mma16816(acc[mb][nq * 2],     ah[mb], bh[nq]);
                    mma16816(acc[mb][nq * 2 + 1], ah[mb], bh[nq] + 2);
                }
        }
        __syncthreads();
    }

    // ---- epilogue ----
    const int ncol0 = warp_n + (lane & 3) * 2;
#pragma unroll
    for (int mb = 0; mb < 2; mb++) {
        int rbase = brow + warp_m + mb * 16 + (lane >> 2);
#pragma unroll
        for (int half = 0; half < 2; half++) {
            int grow = rbase + half * 8;
            if (grow >= N_NODES) continue;
            int q0 = half * 2;
            if (epi_eff == 1) {
                float dv = d_dinv[grow];
#pragma unroll
                for (int nb = 0; nb < 8; nb++) {
                    uint32_t o = pack_h2(acc[mb][nb][q0] * dv, acc[mb][nb][q0 + 1] * dv);
                    *(uint32_t*)(d_g + (size_t)grow * F + ncol0 + nb * 8) = o;
                }
            } else {
                __half* prow = d_act + ACT_STRIDE + (size_t)grow * 128;  // plane 1 = xp
#pragma unroll
                for (int nb = 0; nb < 8; nb++) {
                    int n = ncol0 + nb * 8;
                    float o0 = fmaxf(acc[mb][nb][q0]     + bias[n],     0.0f);
                    float o1 = fmaxf(acc[mb][nb][q0 + 1] + bias[n + 1], 0.0f);
                    *(uint32_t*)(prow + n) = pack_h2(o0, o1);
                }
            }
        }
    }
}

// ---------------- aggregation: 2 warps per node (edge-split + smem combine) ------
// out[v] = relu(dinv[v]*(sum_in g[u] + g[v]) + b); fp16 plane (planeId>=0) or fp32 out
__global__ __launch_bounds__(256) void k_agg(int planeId,
                                             float* __restrict__ out_ext,
                                             const float* __restrict__ bias)
{
    __shared__ float4 sred[4][32];
    const __half* g = d_g;
    int wid = threadIdx.x >> 5, lane = threadIdx.x & 31;
    int pair = wid >> 1;           // 0..3 (node slot)
    int sub = wid & 1;             // 0/1 (which half of edges)
    int v = blockIdx.x * 4 + pair;
    bool valid = v < N_NODES;

    float a0 = 0.f, a1 = 0.f, a2 = 0.f, a3 = 0.f;
    if (valid) {
        int beg = d_rowptr[v], end = d_rowptr[v + 1];
        int h = (end - beg) >> 1;
        int s0 = sub ? beg + h : beg;
        int s1 = sub ? end : beg + h;
        if (sub == 0) {   // self term
            uint2 sv = *(const uint2*)(g + (size_t)v * F + lane * 4);
            float2 p0 = unpack_h2(sv.x), p1 = unpack_h2(sv.y);
            a0 = p0.x; a1 = p0.y; a2 = p1.x; a3 = p1.y;
        }
        int e = s0;
        for (; e + 3 < s1; e += 4) {
            int u0 = __ldg(&d_ssrc[e]);
            int u1 = __ldg(&d_ssrc[e + 1]);
            int u2 = __ldg(&d_ssrc[e + 2]);
            int u3 = __ldg(&d_ssrc[e + 3]);
            uint2 t0 = *(const uint2*)(g + (size_t)u0 * F + lane * 4);
            uint2 t1 = *(const uint2*)(g + (size_t)u1 * F + lane * 4);
            uint2 t2 = *(const uint2*)(g + (size_t)u2 * F + lane * 4);
            uint2 t3 = *(const uint2*)(g + (size_t)u3 * F + lane * 4);
            float2 q0, q1;
            q0 = unpack_h2(t0.x); q1 = unpack_h2(t0.y);
            a0 += q0.x; a1 += q0.y; a2 += q1.x; a3 += q1.y;
            q0 = unpack_h2(t1.x); q1 = unpack_h2(t1.y);
            a0 += q0.x; a1 += q0.y; a2 += q1.x; a3 += q1.y;
            q0 = unpack_h2(t2.x); q1 = unpack_h2(t2.y);
            a0 += q0.x; a1 += q0.y; a2 += q1.x; a3 += q1.y;
            q0 = unpack_h2(t3.x); q1 = unpack_h2(t3.y);
            a0 += q0.x; a1 += q0.y; a2 += q1.x; a3 += q1.y;
        }
        for (; e < s1; e++) {
            int u = __ldg(&d_ssrc[e]);
            uint2 t = *(const uint2*)(g + (size_t)u * F + lane * 4);
            float2 q0 = unpack_h2(t.x), q1 = unpack_h2(t.y);
            a0 += q0.x; a1 += q0.y; a2 += q1.x; a3 += q1.y;
        }
    }

    if (sub == 1) sred[pair][lane] = make_float4(a0, a1, a2, a3);
    __syncthreads();
    if (sub == 0 && valid) {
        float4 r = sred[pair][lane];
        a0 += r.x; a1 += r.y; a2 += r.z; a3 += r.w;

        float dv = d_dinv[v];
        float4 b = *(const float4*)(bias + lane * 4);
        float o0 = fmaxf(fmaf(dv, a0, b.x), 0.0f);
        float o1 = fmaxf(fmaf(dv, a1, b.y), 0.0f);
        float o2 = fmaxf(fmaf(dv, a2, b.z), 0.0f);
        float o3 = fmaxf(fmaf(dv, a3, b.w), 0.0f);

        if (planeId < 0) {
            *(float4*)(out_ext + (size_t)v * F + lane * 4) = make_float4(o0, o1, o2, o3);
        } else {
            __half* prow = d_act + (size_t)planeId * ACT_STRIDE + (size_t)v * 128;
            *(uint2*)(prow + lane * 4) = make_uint2(pack_h2(o0, o1), pack_h2(o2, o3));
        }
    }
}

// ---------------- launch ----------------
extern "C" void kernel_launch(void* const* d_in, const int* in_sizes, int n_in,
                              void* d_out, int out_size)
{
    const float* x     = (const float*)d_in[0];
    const int*   ei    = (const int*)d_in[1];     // int32: JAX x64 disabled
    const float* projW = (const float*)d_in[2];
    const float* projb = (const float*)d_in[3];
    const float* W1    = (const float*)d_in[4];
    const float* b1    = (const float*)d_in[5];
    const float* W2    = (const float*)d_in[6];
    const float* b2    = (const float*)d_in[7];
    const float* W3    = (const float*)d_in[8];
    const float* b3    = (const float*)d_in[9];
    float* out = (float*)d_out;

    const int* src = ei;
    const int* dst = ei + N_EDGES;

    cudaFuncSetAttribute(k_mma, cudaFuncAttributeMaxDynamicSharedMemorySize, SMEM_TOTAL);

    // prep planes + zero cnt (one launch), then deg/dinv, then fused proj+W1 GEMM
    int PREP_ITEMS = PREPX_ITEMS + N_NODES + PREPW_ITEMS;
    k_prep_all<<<(PREP_ITEMS + 255) / 256, 256>>>(x, projW, W1, W2, W3);
    k_hist<<<(N_EDGES + 255) / 256, 256>>>(dst);
    k_dinv<<<(N_NODES + 255) / 256, 256>>>();
    // fused: half 0 -> xp = relu(x@projW+b); half 1 -> g = dinv*(x@W1)
    k_mma<<<2 * GB_TILES, 256, SMEM_TOTAL>>>(0, 0, 0, 1, 0, 0, 1, projb);

    // CSR build (counting sort by dst)
    k_partial<<<NB, SCAN_B>>>();
    k_scan_partial<<<1, 32>>>();
    k_scan_final<<<NB, SCAN_B>>>();
    k_scatter<<<(N_EDGES + 255) / 256, 256>>>(src, dst);

    int AGG_BLOCKS = (N_NODES + 3) / 4;

    // h1 = relu(dinv*agg(g)+b1) -> plane 2
    k_agg<<<AGG_BLOCKS, 256>>>(2, nullptr, b1);

    // layer 2: g = dinv*(xp@W2a + h1@W2b)
    k_mma<<<GB_TILES, 256, SMEM_TOTAL>>>(1, 2, 0, 2, 2, 1, 0, nullptr);
    k_agg<<<AGG_BLOCKS, 256>>>(3, nullptr, b2);   // h2 -> plane 3

    // layer 3: g = dinv*(xp@W3a + h1@W3b + h2@W3c)
    k_mma<<<GB_TILES, 256, SMEM_TOTAL>>>(1, 2, 3, 3, 4, 1, 0, nullptr);
    k_agg<<<AGG_BLOCKS, 256>>>(-1, out, b3);
}

// round 14
// speedup vs baseline: 1.1858x; 1.1858x over previous
#include <cuda_runtime.h>
#include <cuda_fp16.h>
#include <cstdint>

#define N_NODES 100000
#define N_EDGES 1600000
#define F 128
#define SCAN_B 1024
#define NB 98          // ceil(100000/1024)
#define GB_TILES 782   // ceil(100000/128), full 128-col tile
#define ACT_ROWS (N_NODES + 128)          // pad: OOB tile rows stay in-bounds
#define ACT_STRIDE ((size_t)ACT_ROWS * 128)
#define PREPX_ITEMS (N_NODES * 16)
#define PREPW_ITEMS (7 * 128 * 16)

// ---------------- scratch (static __device__, allocation-free) ----------------
// fp16 activation planes, row = 128 fp16 (256B). ids: 0 = x, 1 = xp, 2 = h1, 3 = h2
__device__ __half d_act[4 * ACT_STRIDE];
// weights: 7 slices x [n=128][k=128] fp16
__device__ __half d_wtp[7 * 128 * 128];
__device__ __half d_g[(size_t)N_NODES * F];   // fp16 messages
__device__ float d_dinv[N_NODES];
__device__ int   d_cnt[N_NODES];
__device__ int   d_rowptr[N_NODES + 1];
__device__ int   d_cursor[N_NODES];
__device__ int   d_ssrc[N_EDGES];
__device__ int   d_partial[NB + 1];

__device__ __forceinline__ uint32_t smem_u32(const void* p) {
    uint32_t a;
    asm("{ .reg .u64 t; cvta.to.shared.u64 t, %1; cvt.u32.u64 %0, t; }" : "=r"(a) : "l"(p));
    return a;
}
__device__ __forceinline__ void ldsm_x4(uint32_t* r, uint32_t addr) {
    asm volatile("ldmatrix.sync.aligned.m8n8.x4.shared.b16 {%0,%1,%2,%3}, [%4];"
        : "=r"(r[0]), "=r"(r[1]), "=r"(r[2]), "=r"(r[3]) : "r"(addr));
}
__device__ __forceinline__ void mma16816(float* d, const uint32_t* a, const uint32_t* b) {
    asm volatile(
        "mma.sync.aligned.m16n8k16.row.col.f32.f16.f16.f32 "
        "{%0,%1,%2,%3}, {%4,%5,%6,%7}, {%8,%9}, {%0,%1,%2,%3};"
        : "+f"(d[0]), "+f"(d[1]), "+f"(d[2]), "+f"(d[3])
        : "r"(a[0]), "r"(a[1]), "r"(a[2]), "r"(a[3]), "r"(b[0]), "r"(b[1]));
}
__device__ __forceinline__ void cpa16(uint32_t dst, const void* src) {
    asm volatile("cp.async.cg.shared.global [%0], [%1], 16;" :: "r"(dst), "l"(src));
}
#define CP_COMMIT() asm volatile("cp.async.commit_group;" ::: "memory")
#define CP_WAIT1()  asm volatile("cp.async.wait_group 1;" ::: "memory")
#define CP_WAIT0()  asm volatile("cp.async.wait_group 0;" ::: "memory")

__device__ __forceinline__ uint32_t pack_h2(float x, float y) {
    __half2 t = __floats2half2_rn(x, y);
    return *(uint32_t*)&t;
}
__device__ __forceinline__ float2 unpack_h2(uint32_t v) {
    return __half22float2(*(__half2*)&v);
}

// ---------------- graph preprocessing ----------------
__global__ void k_hist(const int* __restrict__ dst) {
    int e = blockIdx.x * blockDim.x + threadIdx.x;
    if (e < N_EDGES) {
        int d = dst[e];
        if (d >= 0 && d < N_NODES) atomicAdd(&d_cnt[d], 1);
    }
}
__global__ void k_dinv() {
    int v = blockIdx.x * blockDim.x + threadIdx.x;
    if (v < N_NODES) d_dinv[v] = rsqrtf((float)(d_cnt[v] + 1));
}
__global__ void k_partial() {
    __shared__ int s[SCAN_B];
    int i = blockIdx.x * SCAN_B + threadIdx.x;
    s[threadIdx.x] = (i < N_NODES) ? d_cnt[i] : 0;
    __syncthreads();
    for (int off = SCAN_B / 2; off > 0; off >>= 1) {
        if (threadIdx.x < off) s[threadIdx.x] += s[threadIdx.x + off];
        __syncthreads();
    }
    if (threadIdx.x == 0) d_partial[blockIdx.x] = s[0];
}
// warp-shfl exclusive scan over NB partials (single warp)
__global__ void k_scan_partial() {
    int lane = threadIdx.x;   // 32 threads
    int carry = 0;
    for (int base = 0; base < NB; base += 32) {
        int i = base + lane;
        int orig = (i < NB) ? d_partial[i] : 0;
        int v = orig;
#pragma unroll
        for (int off = 1; off < 32; off <<= 1) {
            int t = __shfl_up_sync(0xFFFFFFFFu, v, off);
            if (lane >= off) v += t;
        }
        if (i < NB) d_partial[i] = carry + v - orig;  // exclusive
        carry += __shfl_sync(0xFFFFFFFFu, v, 31);
    }
    if (lane == 0) d_rowptr[N_NODES] = carry;
}
__global__ void k_scan_final() {
    __shared__ int s[SCAN_B];
    int i = blockIdx.x * SCAN_B + threadIdx.x;
    int v = (i < N_NODES) ? d_cnt[i] : 0;
    s[threadIdx.x] = v;
    __syncthreads();
    for (int off = 1; off < SCAN_B; off <<= 1) {
        int t = (threadIdx.x >= off) ? s[threadIdx.x - off] : 0;
        __syncthreads();
        s[threadIdx.x] += t;
        __syncthreads();
    }
    if (i < N_NODES) {
        int excl = s[threadIdx.x] - v + d_partial[blockIdx.x];
        d_rowptr[i] = excl;
        d_cursor[i] = excl;
    }
}
__global__ void k_scatter(const int* __restrict__ src, const int* __restrict__ dst) {
    int e = blockIdx.x * blockDim.x + threadIdx.x;
    if (e < N_EDGES) {
        int d = dst[e];
        int s = src[e];
        if (d >= 0 && d < N_NODES && s >= 0 && s < N_NODES) {
            int pos = atomicAdd(&d_cursor[d], 1);
            d_ssrc[pos] = s;
        }
    }
}

// ---------------- merged prep: x plane + weight planes + zero cnt ----------------
__global__ void k_prep_all(const float* __restrict__ x,
                           const float* __restrict__ pW, const float* __restrict__ w1,
                           const float* __restrict__ w2, const float* __restrict__ w3) {
    int idx = blockIdx.x * blockDim.x + threadIdx.x;
    if (idx < PREPX_ITEMS) {
        int row = idx >> 4;
        int k0 = (idx & 15) * 8;
        const float* src = x + (size_t)row * F + k0;
        uint32_t h[4];
#pragma unroll
        for (int j = 0; j < 4; j++) h[j] = pack_h2(src[j * 2], src[j * 2 + 1]);
        *(uint4*)(d_act + (size_t)row * 128 + k0) = make_uint4(h[0], h[1], h[2], h[3]);
    } else if (idx < PREPX_ITEMS + N_NODES) {
        d_cnt[idx - PREPX_ITEMS] = 0;
    } else {
        int j = idx - PREPX_ITEMS - N_NODES;
        if (j < PREPW_ITEMS) {
            int slice = j >> 11;
            int rem = j & 2047;
            int n = rem >> 4;
            int k0 = (rem & 15) * 8;
            const float* src; int kg0;
            if (slice == 0)      { src = pW; kg0 = 0; }
            else if (slice == 1) { src = w1; kg0 = 0; }
            else if (slice < 4)  { src = w2; kg0 = (slice - 2) * 128; }
            else                 { src = w3; kg0 = (slice - 4) * 128; }
            uint32_t hi[4];
#pragma unroll
            for (int jj = 0; jj < 4; jj++) {
                float a = src[(size_t)(kg0 + k0 + jj * 2) * 128 + n];
                float b = src[(size_t)(kg0 + k0 + jj * 2 + 1) * 128 + n];
                hi[jj] = pack_h2(a, b);
            }
            *(uint4*)(d_wtp + (size_t)slice * 128 * 128 + (size_t)n * 128 + k0) =
                make_uint4(hi[0], hi[1], hi[2], hi[3]);
        }
    }
}

// ---------------- HMMA GEMM, fp16 single-product, 2-stage cp.async, tile 128x128 ----
// stage s at s*32768: A[128 rows][128B] (16KB), W[128 rows][128B] at +16384 (16KB)
#define STAGE_BYTES 32768
#define SMEM_TOTAL (2 * STAGE_BYTES)

// fused=1: grid 2*GB_TILES; half 0 -> wslice0+0, epi 2 (xp); half 1 -> wslice0+1, epi 1 (g)
// epi: 1 = d_g fp16, scale row by dinv; 2 = xp fp16 plane, bias + relu
__global__ __launch_bounds__(256, 2)
void k_mma(int aid0, int aid1, int aid2, int nslices,
           int wslice0, int epi, int fused, const float* __restrict__ bias)
{
    extern __shared__ char smem[];
    const uint32_t sb = smem_u32(smem);
    const int tid = threadIdx.x;
    const int lane = tid & 31;
    const int warp = tid >> 5;
    const int half_id = fused ? (blockIdx.x >= GB_TILES ? 1 : 0) : 0;
    const int bx = fused ? (blockIdx.x - half_id * GB_TILES) : blockIdx.x;
    const int brow = bx * 128;
    const int wbase = wslice0 + half_id;
    const int epi_eff = fused ? (half_id ? 1 : 2) : epi;
    const int warp_m = (warp >> 1) * 32;
    const int warp_n = (warp & 1) * 64;

    float acc[2][8][4];
#pragma unroll
    for (int mb = 0; mb < 2; mb++)
#pragma unroll
        for (int nb = 0; nb < 8; nb++)
#pragma unroll
            for (int q = 0; q < 4; q++) acc[mb][nb][q] = 0.0f;

    const int aids[3] = {aid0, aid1, aid2};
    const int T = nslices * 2;          // k64 chunks

    // staging thread mapping
    const int st_row = tid >> 3;        // 0..31 (+32 per it)
    const int st_ch  = tid & 7;

    // ldmatrix address components
    const int rowA = warp_m + (lane & 15);
    const int swA = rowA & 7;
    const int chA = lane >> 4;
    const int rowB = warp_n + (lane & 7) + ((lane >> 4) << 3);
    const int swB = lane & 7;
    const int chB = (lane >> 3) & 1;

    // ---- stage chunk t (k64 half c of slice s) into buffer buf ----
    auto stage = [&](int t, int buf) {
        int s = t >> 1, c = t & 1;
        const __half* Ag = d_act + (size_t)aids[s] * ACT_STRIDE;
        const __half* Wg = d_wtp + (size_t)(wbase + s) * 128 * 128;
        uint32_t abuf = sb + buf * STAGE_BYTES;
        uint32_t wbuf = abuf + 16384;
#pragma unroll
        for (int it = 0; it < 4; it++) {
            int row = st_row + it * 32;
            const char* src = (const char*)(Ag + (size_t)(brow + row) * 128 + c * 64) + st_ch * 16;
            cpa16(abuf + row * 128 + ((st_ch ^ (row & 7)) << 4), src);
        }
#pragma unroll
        for (int it = 0; it < 4; it++) {
            int n = st_row + it * 32;   // 0..127
            const __half* wrow = Wg + (size_t)n * 128 + c * 64;
            cpa16(wbuf + n * 128 + ((st_ch ^ (n & 7)) << 4), (const char*)wrow + st_ch * 16);
        }
    };

    stage(0, 0); CP_COMMIT();

    for (int t = 0; t < T; t++) {
        const int buf = t & 1;
        if (t + 1 < T) { stage(t + 1, buf ^ 1); CP_COMMIT(); CP_WAIT1(); }
        else           { CP_WAIT0(); }
        __syncthreads();

        const uint32_t abase = sb + buf * STAGE_BYTES + rowA * 128;
        const uint32_t bbase = sb + buf * STAGE_BYTES + 16384 + rowB * 128;
#pragma unroll
        for (int ks = 0; ks < 4; ks++) {
            uint32_t ah[2][4];
            const int lA = ks * 2 + chA;
#pragma unroll
            for (int mb = 0; mb < 2; mb++)
                ldsm_x4(ah[mb], abase + mb * 2048 + ((lA ^ swA) << 4));
            const int lB = ks * 2 + chB;
            uint32_t bh[4][4];
#pragma unroll
            for (int nq = 0; nq < 4; nq++)
                ldsm_x4(bh[nq], bbase + nq * 2048 + ((lB ^ swB) << 4));
            // 16 MMAs, 16 distinct accumulators
#pragma unroll
            for (int nq = 0; nq < 4; nq++)
#pragma unroll
                for (int mb = 0; mb < 2; mb++) {
                    mma16816(acc[mb][nq * 2],     ah[mb], bh[nq]);
                    mma16816(acc[mb][nq * 2 + 1], ah[mb], bh[nq] + 2);
                }
        }
        __syncthreads();
    }

    // ---- epilogue ----
    const int ncol0 = warp_n + (lane & 3) * 2;
#pragma unroll
    for (int mb = 0; mb < 2; mb++) {
        int rbase = brow + warp_m + mb * 16 + (lane >> 2);
#pragma unroll
        for (int half = 0; half < 2; half++) {
            int grow = rbase + half * 8;
            if (grow >= N_NODES) continue;
            int q0 = half * 2;
            if (epi_eff == 1) {
                float dv = d_dinv[grow];
#pragma unroll
                for (int nb = 0; nb < 8; nb++) {
                    uint32_t o = pack_h2(acc[mb][nb][q0] * dv, acc[mb][nb][q0 + 1] * dv);
                    *(uint32_t*)(d_g + (size_t)grow * F + ncol0 + nb * 8) = o;
                }
            } else {
                __half* prow = d_act + ACT_STRIDE + (size_t)grow * 128;  // plane 1 = xp
#pragma unroll
                for (int nb = 0; nb < 8; nb++) {
                    int n = ncol0 + nb * 8;
                    float o0 = fmaxf(acc[mb][nb][q0]     + bias[n],     0.0f);
                    float o1 = fmaxf(acc[mb][nb][q0 + 1] + bias[n + 1], 0.0f);
                    *(uint32_t*)(prow + n) = pack_h2(o0, o1);
                }
            }
        }
    }
}

// ---------------- aggregation (R12 version: 1 warp/node, independent) ----------
// out[v] = relu(dinv[v]*(sum_in g[u] + g[v]) + b); fp16 plane (planeId>=0) or fp32 out
__global__ __launch_bounds__(256) void k_agg(int planeId,
                                             float* __restrict__ out_ext,
                                             const float* __restrict__ bias)
{
    const __half* g = d_g;
    int v = (blockIdx.x * blockDim.x + threadIdx.x) >> 5;
    int lane = threadIdx.x & 31;
    if (v >= N_NODES) return;

    int beg = d_rowptr[v];
    int end = d_rowptr[v + 1];

    uint2 sv = *(const uint2*)(g + (size_t)v * F + lane * 4);   // self term
    float2 p0 = unpack_h2(sv.x), p1 = unpack_h2(sv.y);
    float a0 = p0.x, a1 = p0.y, a2 = p1.x, a3 = p1.y;

    int e = beg;
    for (; e + 3 < end; e += 4) {
        int u0 = __ldg(&d_ssrc[e]);
        int u1 = __ldg(&d_ssrc[e + 1]);
        int u2 = __ldg(&d_ssrc[e + 2]);
        int u3 = __ldg(&d_ssrc[e + 3]);
        uint2 t0 = *(const uint2*)(g + (size_t)u0 * F + lane * 4);
        uint2 t1 = *(const uint2*)(g + (size_t)u1 * F + lane * 4);
        uint2 t2 = *(const uint2*)(g + (size_t)u2 * F + lane * 4);
        uint2 t3 = *(const uint2*)(g + (size_t)u3 * F + lane * 4);
        float2 q0, q1;
        q0 = unpack_h2(t0.x); q1 = unpack_h2(t0.y);
        a0 += q0.x; a1 += q0.y; a2 += q1.x; a3 += q1.y;
        q0 = unpack_h2(t1.x); q1 = unpack_h2(t1.y);
        a0 += q0.x; a1 += q0.y; a2 += q1.x; a3 += q1.y;
        q0 = unpack_h2(t2.x); q1 = unpack_h2(t2.y);
        a0 += q0.x; a1 += q0.y; a2 += q1.x; a3 += q1.y;
        q0 = unpack_h2(t3.x); q1 = unpack_h2(t3.y);
        a0 += q0.x; a1 += q0.y; a2 += q1.x; a3 += q1.y;
    }
    for (; e < end; e++) {
        int u = __ldg(&d_ssrc[e]);
        uint2 t = *(const uint2*)(g + (size_t)u * F + lane * 4);
        float2 q0 = unpack_h2(t.x), q1 = unpack_h2(t.y);
        a0 += q0.x; a1 += q0.y; a2 += q1.x; a3 += q1.y;
    }

    float dv = d_dinv[v];
    float4 b = *(const float4*)(bias + lane * 4);
    float o0 = fmaxf(fmaf(dv, a0, b.x), 0.0f);
    float o1 = fmaxf(fmaf(dv, a1, b.y), 0.0f);
    float o2 = fmaxf(fmaf(dv, a2, b.z), 0.0f);
    float o3 = fmaxf(fmaf(dv, a3, b.w), 0.0f);

    if (planeId < 0) {
        *(float4*)(out_ext + (size_t)v * F + lane * 4) = make_float4(o0, o1, o2, o3);
    } else {
        __half* prow = d_act + (size_t)planeId * ACT_STRIDE + (size_t)v * 128;
        *(uint2*)(prow + lane * 4) = make_uint2(pack_h2(o0, o1), pack_h2(o2, o3));
    }
}

// ---------------- launch ----------------
extern "C" void kernel_launch(void* const* d_in, const int* in_sizes, int n_in,
                              void* d_out, int out_size)
{
    const float* x     = (const float*)d_in[0];
    const int*   ei    = (const int*)d_in[1];     // int32: JAX x64 disabled
    const float* projW = (const float*)d_in[2];
    const float* projb = (const float*)d_in[3];
    const float* W1    = (const float*)d_in[4];
    const float* b1    = (const float*)d_in[5];
    const float* W2    = (const float*)d_in[6];
    const float* b2    = (const float*)d_in[7];
    const float* W3    = (const float*)d_in[8];
    const float* b3    = (const float*)d_in[9];
    float* out = (float*)d_out;

    const int* src = ei;
    const int* dst = ei + N_EDGES;

    cudaFuncSetAttribute(k_mma, cudaFuncAttributeMaxDynamicSharedMemorySize, SMEM_TOTAL);

    // prep planes + zero cnt (one launch), then deg/dinv, then fused proj+W1 GEMM
    int PREP_ITEMS = PREPX_ITEMS + N_NODES + PREPW_ITEMS;
    k_prep_all<<<(PREP_ITEMS + 255) / 256, 256>>>(x, projW, W1, W2, W3);
    k_hist<<<(N_EDGES + 255) / 256, 256>>>(dst);
    k_dinv<<<(N_NODES + 255) / 256, 256>>>();
    // fused: half 0 -> xp = relu(x@projW+b); half 1 -> g = dinv*(x@W1)
    k_mma<<<2 * GB_TILES, 256, SMEM_TOTAL>>>(0, 0, 0, 1, 0, 0, 1, projb);

    // CSR build (counting sort by dst)
    k_partial<<<NB, SCAN_B>>>();
    k_scan_partial<<<1, 32>>>();
    k_scan_final<<<NB, SCAN_B>>>();
    k_scatter<<<(N_EDGES + 255) / 256, 256>>>(src, dst);

    int AGG_BLOCKS = (N_NODES * 32 + 255) / 256;

    // h1 = relu(dinv*agg(g)+b1) -> plane 2
    k_agg<<<AGG_BLOCKS, 256>>>(2, nullptr, b1);

    // layer 2: g = dinv*(xp@W2a + h1@W2b)
    k_mma<<<GB_TILES, 256, SMEM_TOTAL>>>(1, 2, 0, 2, 2, 1, 0, nullptr);
    k_agg<<<AGG_BLOCKS, 256>>>(3, nullptr, b2);   // h2 -> plane 3

    // layer 3: g = dinv*(xp@W3a + h1@W3b + h2@W3c)
    k_mma<<<GB_TILES, 256, SMEM_TOTAL>>>(1, 2, 3, 3, 4, 1, 0, nullptr);
    k_agg<<<AGG_BLOCKS, 256>>>(-1, out, b3);
}